// round 2
// baseline (speedup 1.0000x reference)
#include <cuda_runtime.h>
#include <math.h>

// ---------------- problem constants ----------------
#define BATCH 256
// conv1: in [256,3,250,250], w [6,3,5,5], s2 p1 -> [256,6,124,124]
// pool1 -> [256,6,123,123]
// conv2: w [15,6,3,3], s2 p1 -> [256,15,62,62]
// pool2 -> [256,15,61,61]  (flatten K = 15*61*61 = 55815)
#define KDIM 55815
#define KSPLIT 37
#define KCHUNK 1536

// ---------------- scratch (static device arrays; no allocation) ----------------
__device__ float g_conv1[(size_t)BATCH * 6 * 124 * 124];   // 94.5 MB
__device__ float g_pool1[(size_t)BATCH * 6 * 123 * 123];   // 93.0 MB
__device__ float g_conv2[(size_t)BATCH * 15 * 62 * 62];    // 59.0 MB
__device__ float g_pool2[(size_t)BATCH * 15 * 61 * 61];    // 57.2 MB (fc1 "A")
__device__ float g_part[(size_t)KSPLIT * BATCH * 120];     // 4.5 MB
__device__ float g_h1[BATCH * 120];
__device__ float g_feat[BATCH * 84];
__device__ float g_probs[BATCH];

// ---------------- conv1 + relu ----------------
// block (16,8): tile 64(ow) x 8(oh); thread: 4 ow x 6 oc
__global__ __launch_bounds__(128) void conv1_kernel(
    const float* __restrict__ x, const float* __restrict__ w,
    const float* __restrict__ bias)
{
    __shared__ float sIn[3][19][132];
    __shared__ float sW[450];
    const int b = blockIdx.z;
    const int ow0 = blockIdx.x * 64;
    const int oh0 = blockIdx.y * 8;
    const int tx = threadIdx.x, ty = threadIdx.y;
    const int tid = ty * 16 + tx;

    for (int i = tid; i < 450; i += 128) sW[i] = w[i];

    const int ih0 = oh0 * 2 - 1;
    const int iw0 = ow0 * 2 - 1;
    const float* xb = x + (size_t)b * 3 * 250 * 250;
    for (int i = tid; i < 3 * 19 * 131; i += 128) {
        int c = i / (19 * 131);
        int rem = i % (19 * 131);
        int r = rem / 131, col = rem % 131;
        int ih = ih0 + r, iw = iw0 + col;
        float v = 0.f;
        if (ih >= 0 && ih < 250 && iw >= 0 && iw < 250)
            v = xb[(c * 250 + ih) * 250 + iw];
        sIn[c][r][col] = v;
    }
    __syncthreads();

    float acc[6][4];
    #pragma unroll
    for (int oc = 0; oc < 6; oc++) {
        float bv = bias[oc];
        #pragma unroll
        for (int j = 0; j < 4; j++) acc[oc][j] = bv;
    }

    #pragma unroll 1
    for (int c = 0; c < 3; c++) {
        #pragma unroll 1
        for (int kh = 0; kh < 5; kh++) {
            float in[11];
            const float* row = &sIn[c][ty * 2 + kh][tx * 8];
            #pragma unroll
            for (int i = 0; i < 11; i++) in[i] = row[i];
            #pragma unroll
            for (int oc = 0; oc < 6; oc++) {
                const float* wp = &sW[((oc * 3 + c) * 5 + kh) * 5];
                #pragma unroll
                for (int kw = 0; kw < 5; kw++) {
                    float wv = wp[kw];
                    #pragma unroll
                    for (int j = 0; j < 4; j++)
                        acc[oc][j] = fmaf(in[2 * j + kw], wv, acc[oc][j]);
                }
            }
        }
    }

    const int oh = oh0 + ty;
    if (oh < 124) {
        #pragma unroll
        for (int oc = 0; oc < 6; oc++) {
            float* op = g_conv1 + (((size_t)b * 6 + oc) * 124 + oh) * 124;
            #pragma unroll
            for (int j = 0; j < 4; j++) {
                int ow = ow0 + tx * 4 + j;
                if (ow < 124) op[ow] = fmaxf(acc[oc][j], 0.f);
            }
        }
    }
}

// ---------------- maxpool 2x2 stride 1 (VALID) ----------------
__device__ __forceinline__ void maxpool_impl(
    const float* __restrict__ in, float* __restrict__ out,
    int BC, int Hin, int Win)
{
    const int Ho = Hin - 1, Wo = Win - 1;
    const size_t total = (size_t)BC * Ho * Wo;
    const size_t stride = (size_t)gridDim.x * blockDim.x;
    for (size_t idx = (size_t)blockIdx.x * blockDim.x + threadIdx.x;
         idx < total; idx += stride) {
        int wo = (int)(idx % Wo);
        size_t t = idx / Wo;
        int ho = (int)(t % Ho);
        size_t bc = t / Ho;
        const float* p = in + (bc * Hin + ho) * Win + wo;
        out[idx] = fmaxf(fmaxf(p[0], p[1]), fmaxf(p[Win], p[Win + 1]));
    }
}
__global__ void maxpool1_kernel() { maxpool_impl(g_conv1, g_pool1, BATCH * 6, 124, 124); }
__global__ void maxpool2_kernel() { maxpool_impl(g_conv2, g_pool2, BATCH * 15, 62, 62); }

// ---------------- conv2 + relu ----------------
// block (16,8): tile 64(ow) x 8(oh); thread: 4 ow x 15 oc; loop input channels
__global__ __launch_bounds__(128) void conv2_kernel(
    const float* __restrict__ w, const float* __restrict__ bias)
{
    __shared__ float sIn[17][132];
    __shared__ float sW[810];
    const int b = blockIdx.z;
    const int oh0 = blockIdx.y * 8;
    const int tx = threadIdx.x, ty = threadIdx.y;
    const int tid = ty * 16 + tx;

    for (int i = tid; i < 810; i += 128) sW[i] = w[i];

    float acc[15][4];
    #pragma unroll
    for (int oc = 0; oc < 15; oc++) {
        float bv = bias[oc];
        #pragma unroll
        for (int j = 0; j < 4; j++) acc[oc][j] = bv;
    }

    const int ih0 = oh0 * 2 - 1;
    #pragma unroll 1
    for (int c = 0; c < 6; c++) {
        __syncthreads();
        const float* pin = g_pool1 + ((size_t)b * 6 + c) * 123 * 123;
        for (int i = tid; i < 17 * 129; i += 128) {
            int r = i / 129, col = i % 129;
            int ih = ih0 + r, iw = col - 1;
            float v = 0.f;
            if (ih >= 0 && ih < 123 && iw >= 0 && iw < 123)
                v = pin[ih * 123 + iw];
            sIn[r][col] = v;
        }
        __syncthreads();
        #pragma unroll 1
        for (int kh = 0; kh < 3; kh++) {
            float in[9];
            const float* row = &sIn[ty * 2 + kh][tx * 8];
            #pragma unroll
            for (int i = 0; i < 9; i++) in[i] = row[i];
            #pragma unroll
            for (int oc = 0; oc < 15; oc++) {
                const float* wp = &sW[((oc * 6 + c) * 3 + kh) * 3];
                #pragma unroll
                for (int kw = 0; kw < 3; kw++) {
                    float wv = wp[kw];
                    #pragma unroll
                    for (int j = 0; j < 4; j++)
                        acc[oc][j] = fmaf(in[2 * j + kw], wv, acc[oc][j]);
                }
            }
        }
    }

    const int oh = oh0 + ty;
    if (oh < 62) {
        #pragma unroll
        for (int oc = 0; oc < 15; oc++) {
            float* op = g_conv2 + (((size_t)b * 15 + oc) * 62 + oh) * 62;
            #pragma unroll
            for (int j = 0; j < 4; j++) {
                int ow = tx * 4 + j;
                if (ow < 62) op[ow] = fmaxf(acc[oc][j], 0.f);
            }
        }
    }
}

// ---------------- fc1 split-K GEMM: [256,55815] x [120,55815]^T ----------------
// grid (4 M-tiles, 37 K-chunks) = 148 blocks; tile 64M x 120N; 256 threads
__global__ __launch_bounds__(256) void fc1_kernel(const float* __restrict__ W)
{
    __shared__ float sA[64][17];
    __shared__ float sW[128][17];
    const int m0 = blockIdx.x * 64;
    const int ks = blockIdx.y;
    const int kbeg = ks * KCHUNK;
    const int kend = (kbeg + KCHUNK < KDIM) ? kbeg + KCHUNK : KDIM;
    const int tid = threadIdx.x;
    const int tx = tid & 15, ty = tid >> 4;

    float acc[4][8];
    #pragma unroll
    for (int i = 0; i < 4; i++)
        #pragma unroll
        for (int j = 0; j < 8; j++) acc[i][j] = 0.f;

    const float* A = g_pool2;

    for (int k0 = kbeg; k0 < kend; k0 += 16) {
        #pragma unroll
        for (int i = tid; i < 64 * 16; i += 256) {
            int m = i >> 4, kk = i & 15;
            int k = k0 + kk;
            sA[m][kk] = (k < kend) ? A[(size_t)(m0 + m) * KDIM + k] : 0.f;
        }
        #pragma unroll
        for (int i = tid; i < 128 * 16; i += 256) {
            int n = i >> 4, kk = i & 15;
            int k = k0 + kk;
            sW[n][kk] = (n < 120 && k < kend) ? W[(size_t)n * KDIM + k] : 0.f;
        }
        __syncthreads();
        #pragma unroll
        for (int kk = 0; kk < 16; kk++) {
            float a[4], wv[8];
            #pragma unroll
            for (int i = 0; i < 4; i++) a[i] = sA[ty * 4 + i][kk];
            #pragma unroll
            for (int j = 0; j < 8; j++) wv[j] = sW[tx + 16 * j][kk];
            #pragma unroll
            for (int i = 0; i < 4; i++)
                #pragma unroll
                for (int j = 0; j < 8; j++)
                    acc[i][j] = fmaf(a[i], wv[j], acc[i][j]);
        }
        __syncthreads();
    }

    #pragma unroll
    for (int i = 0; i < 4; i++) {
        int m = m0 + ty * 4 + i;
        #pragma unroll
        for (int j = 0; j < 8; j++) {
            int n = tx + 16 * j;
            if (n < 120)
                g_part[((size_t)ks * BATCH + m) * 120 + n] = acc[i][j];
        }
    }
}

__global__ void fc1_reduce_kernel(const float* __restrict__ fc1_b)
{
    int idx = blockIdx.x * blockDim.x + threadIdx.x;
    if (idx >= BATCH * 120) return;
    int n = idx % 120;
    float s = fc1_b[n];
    #pragma unroll 1
    for (int ks = 0; ks < KSPLIT; ks++)
        s += g_part[(size_t)ks * BATCH * 120 + idx];
    g_h1[idx] = fmaxf(s, 0.f);
}

// ---------------- fc2 + fc3 + ParameterizedLayer + sigmoid ----------------
__global__ __launch_bounds__(128) void head_kernel(
    const float* __restrict__ fc2_w, const float* __restrict__ fc2_b,
    const float* __restrict__ fc3_w, const float* __restrict__ fc3_b,
    const float* __restrict__ pl_w, const float* __restrict__ pl_b,
    const float* __restrict__ pl_scale, const float* __restrict__ pl_bias)
{
    const int m = blockIdx.x;
    const int t = threadIdx.x;
    __shared__ float sh[120];
    __shared__ float sfeat[84];
    if (t < 120) sh[t] = g_h1[m * 120 + t];
    __syncthreads();
    if (t < 84) {
        float s = fc2_b[t];
        const float* wr = fc2_w + t * 120;
        #pragma unroll
        for (int k = 0; k < 120; k++) s = fmaf(sh[k], wr[k], s);
        g_feat[m * 84 + t] = s;
        sfeat[t] = s * fc3_w[t];
    }
    __syncthreads();
    if (t == 0) {
        float l = fc3_b[0];
        #pragma unroll
        for (int k = 0; k < 84; k++) l += sfeat[k];
        float z = tanhf(l * pl_w[0] + pl_b[0]) * pl_scale[0] + pl_bias[0];
        g_probs[m] = 1.f / (1.f + expf(-z));
    }
}

// ---------------- cosine-sign adjacency + degree-weighted aggregation ----------------
// sim >= 0  <=>  dot >= 0 (denominator strictly positive); exclude diagonal.
__global__ __launch_bounds__(256) void graph_kernel(float* __restrict__ out)
{
    const int i = blockIdx.x;
    const int j = threadIdx.x;
    __shared__ float sf[84];
    __shared__ float rc[8], rs[8];
    if (j < 84) sf[j] = g_feat[i * 84 + j];
    __syncthreads();

    const float* fj = g_feat + j * 84;
    float dot = 0.f;
    #pragma unroll
    for (int k = 0; k < 84; k++) dot = fmaf(sf[k], fj[k], dot);

    const bool adj = (dot >= 0.f) && (j != i);
    float c = adj ? 1.f : 0.f;
    float s = adj ? g_probs[j] : 0.f;
    #pragma unroll
    for (int o = 16; o > 0; o >>= 1) {
        c += __shfl_down_sync(0xffffffffu, c, o);
        s += __shfl_down_sync(0xffffffffu, s, o);
    }
    const int lane = j & 31, wrp = j >> 5;
    if (lane == 0) { rc[wrp] = c; rs[wrp] = s; }
    __syncthreads();
    if (j == 0) {
        float deg = 0.f, ss = 0.f;
        #pragma unroll
        for (int w2 = 0; w2 < 8; w2++) { deg += rc[w2]; ss += rs[w2]; }
        float neigh = (deg > 0.f) ? ss / fmaxf(deg, 1.f) : 0.f;
        float agg = (g_probs[i] + neigh) / (1.f + deg);
        out[2 * i]     = agg;
        out[2 * i + 1] = 1.f - agg;
    }
}

// ---------------- launch ----------------
extern "C" void kernel_launch(void* const* d_in, const int* in_sizes, int n_in,
                              void* d_out, int out_size)
{
    const float* x       = (const float*)d_in[0];
    const float* conv1_w = (const float*)d_in[1];
    const float* conv1_b = (const float*)d_in[2];
    const float* conv2_w = (const float*)d_in[3];
    const float* conv2_b = (const float*)d_in[4];
    const float* fc1_w   = (const float*)d_in[5];
    const float* fc1_b   = (const float*)d_in[6];
    const float* fc2_w   = (const float*)d_in[7];
    const float* fc2_b   = (const float*)d_in[8];
    const float* fc3_w   = (const float*)d_in[9];
    const float* fc3_b   = (const float*)d_in[10];
    const float* pl_w    = (const float*)d_in[11];
    const float* pl_b    = (const float*)d_in[12];
    const float* pl_scale= (const float*)d_in[13];
    const float* pl_bias = (const float*)d_in[14];
    float* out = (float*)d_out;

    conv1_kernel<<<dim3(2, 16, BATCH), dim3(16, 8)>>>(x, conv1_w, conv1_b);
    maxpool1_kernel<<<2048, 256>>>();
    conv2_kernel<<<dim3(1, 8, BATCH), dim3(16, 8)>>>(conv2_w, conv2_b);
    maxpool2_kernel<<<2048, 256>>>();
    fc1_kernel<<<dim3(4, KSPLIT), 256>>>(fc1_w);
    fc1_reduce_kernel<<<(BATCH * 120 + 255) / 256, 256>>>(fc1_b);
    head_kernel<<<BATCH, 128>>>(fc2_w, fc2_b, fc3_w, fc3_b, pl_w, pl_b, pl_scale, pl_bias);
    graph_kernel<<<BATCH, 256>>>(out);
}

// round 3
// speedup vs baseline: 1.1725x; 1.1725x over previous
#include <cuda_runtime.h>
#include <math.h>

// ---------------- problem constants ----------------
#define BATCH 256
// conv1: in [256,3,250,250], w [6,3,5,5], s2 p1 -> [256,6,124,124]
// pool1 (fused) -> [256,6,123,123]
// conv2: w [15,6,3,3], s2 p1 -> [256,15,62,62]
// pool2 (fused) -> [256,15,61,61]  (flatten K = 15*61*61 = 55815)
#define KDIM 55815
#define KSPLIT 37
#define KCHUNK 1536

// ---------------- scratch (static device arrays; no allocation) ----------------
__device__ float g_pool1[(size_t)BATCH * 6 * 123 * 123];   // 93.0 MB
__device__ float g_pool2[(size_t)BATCH * 15 * 61 * 61];    // 57.2 MB (fc1 "A")
__device__ float g_part[(size_t)KSPLIT * BATCH * 120];     // 4.5 MB
__device__ float g_h1[BATCH * 120];
__device__ float g_feat[BATCH * 84];
__device__ float g_probs[BATCH];

// ---------------- f32x2 helpers ----------------
__device__ __forceinline__ unsigned long long pk(float lo, float hi) {
    unsigned long long r;
    asm("mov.b64 %0, {%1, %2};" : "=l"(r) : "f"(lo), "f"(hi));
    return r;
}
__device__ __forceinline__ void ffma2(unsigned long long& d,
                                      unsigned long long a, unsigned long long b) {
    asm("fma.rn.f32x2 %0, %1, %2, %0;" : "+l"(d) : "l"(a), "l"(b));
}
__device__ __forceinline__ float2 upk(unsigned long long v) {
    float2 r;
    asm("mov.b64 {%0, %1}, %2;" : "=f"(r.x), "=f"(r.y) : "l"(v));
    return r;
}

// ---------------- conv1 + relu + fused maxpool(2,2,s1) ----------------
// block (16,8): conv tile 64(ow) x 8(oh); pool tile 63 x 7 (overlapping grid)
// f32x2 over oc-pairs: acc2[p][j], lanes = (oc=2p, oc=2p+1)
__global__ __launch_bounds__(128) void conv1_kernel(
    const float* __restrict__ x, const float* __restrict__ w,
    const float* __restrict__ bias)
{
    __shared__ float sIn[3][19][132];
    __shared__ unsigned long long sW2[3][5][5][3];   // [c][kh][kw][ocpair]
    __shared__ float sOut[6][8][65];
    const int b = blockIdx.z;
    const int ow0 = blockIdx.x * 60;
    const int oh0 = blockIdx.y * 7;
    const int tx = threadIdx.x, ty = threadIdx.y;
    const int tid = ty * 16 + tx;

    // pack weights {w[2p], w[2p+1]} per (c,kh,kw)
    for (int i = tid; i < 225; i += 128) {
        int p = i % 3;
        int kw = (i / 3) % 5;
        int kh = (i / 15) % 5;
        int c = i / 75;
        float w0 = w[(((2 * p) * 3 + c) * 5 + kh) * 5 + kw];
        float w1 = w[(((2 * p + 1) * 3 + c) * 5 + kh) * 5 + kw];
        sW2[c][kh][kw][p] = pk(w0, w1);
    }

    const int ih0 = oh0 * 2 - 1;
    const int iw0 = ow0 * 2 - 1;
    const float* xb = x + (size_t)b * 3 * 250 * 250;
    for (int i = tid; i < 3 * 19 * 131; i += 128) {
        int c = i / (19 * 131);
        int rem = i % (19 * 131);
        int r = rem / 131, col = rem % 131;
        int ih = ih0 + r, iw = iw0 + col;
        float v = 0.f;
        if (ih >= 0 && ih < 250 && iw >= 0 && iw < 250)
            v = xb[(c * 250 + ih) * 250 + iw];
        sIn[c][r][col] = v;
    }
    __syncthreads();

    unsigned long long acc2[3][4];
    #pragma unroll
    for (int p = 0; p < 3; p++) {
        unsigned long long bv = pk(bias[2 * p], bias[2 * p + 1]);
        #pragma unroll
        for (int j = 0; j < 4; j++) acc2[p][j] = bv;
    }

    #pragma unroll 1
    for (int c = 0; c < 3; c++) {
        #pragma unroll 1
        for (int kh = 0; kh < 5; kh++) {
            const float* row = &sIn[c][ty * 2 + kh][tx * 8];
            unsigned long long b2[11];
            #pragma unroll
            for (int i = 0; i < 11; i++) { float v = row[i]; b2[i] = pk(v, v); }
            #pragma unroll
            for (int p = 0; p < 3; p++) {
                #pragma unroll
                for (int kw = 0; kw < 5; kw++) {
                    unsigned long long wv = sW2[c][kh][kw][p];
                    #pragma unroll
                    for (int j = 0; j < 4; j++)
                        ffma2(acc2[p][j], b2[2 * j + kw], wv);
                }
            }
        }
    }

    // relu -> smem
    #pragma unroll
    for (int p = 0; p < 3; p++) {
        #pragma unroll
        for (int j = 0; j < 4; j++) {
            float2 v = upk(acc2[p][j]);
            sOut[2 * p][ty][tx * 4 + j] = fmaxf(v.x, 0.f);
            sOut[2 * p + 1][ty][tx * 4 + j] = fmaxf(v.y, 0.f);
        }
    }
    __syncthreads();

    // fused 2x2 s1 maxpool -> g_pool1 [256,6,123,123]
    if (ty < 7) {
        int pr = oh0 + ty;
        if (pr < 123) {
            #pragma unroll
            for (int oc = 0; oc < 6; oc++) {
                #pragma unroll
                for (int j = 0; j < 4; j++) {
                    int cl = tx * 4 + j;
                    if (cl > 62) continue;
                    int pc = ow0 + cl;
                    if (pc >= 123) continue;
                    float m = fmaxf(fmaxf(sOut[oc][ty][cl], sOut[oc][ty][cl + 1]),
                                    fmaxf(sOut[oc][ty + 1][cl], sOut[oc][ty + 1][cl + 1]));
                    g_pool1[(((size_t)b * 6 + oc) * 123 + pr) * 123 + pc] = m;
                }
            }
        }
    }
}

// ---------------- conv2 + relu + fused maxpool(2,2,s1) ----------------
// block (16,8): conv tile 62(ow full) x 8(oh); pool tile 61 x 7
// f32x2 over ow-pairs: acc2[oc][pair], lanes = (ow 2q, ow 2q+1)
__global__ __launch_bounds__(128) void conv2_kernel(
    const float* __restrict__ w, const float* __restrict__ bias)
{
    __shared__ float sIn[17][132];
    __shared__ unsigned long long sW2[15][6][3][3];  // duplicated {w,w}
    __shared__ float sOut[15][8][63];
    const int b = blockIdx.z;
    const int oh0 = blockIdx.y * 7;
    const int tx = threadIdx.x, ty = threadIdx.y;
    const int tid = ty * 16 + tx;

    for (int i = tid; i < 810; i += 128) {
        float wv = w[i];
        int kw = i % 3, kh = (i / 3) % 3, c = (i / 9) % 6, oc = i / 54;
        sW2[oc][c][kh][kw] = pk(wv, wv);
    }

    unsigned long long acc2[15][2];
    #pragma unroll
    for (int oc = 0; oc < 15; oc++) {
        // bias added at store time to keep init cheap? No: init directly
        acc2[oc][0] = 0ull; acc2[oc][1] = 0ull;
    }

    const int ih0 = oh0 * 2 - 1;
    #pragma unroll 1
    for (int c = 0; c < 6; c++) {
        __syncthreads();
        const float* pin = g_pool1 + ((size_t)b * 6 + c) * 123 * 123;
        for (int i = tid; i < 17 * 129; i += 128) {
            int r = i / 129, col = i % 129;
            int ih = ih0 + r, iw = col - 1;
            float v = 0.f;
            if (ih >= 0 && ih < 123 && iw >= 0 && iw < 123)
                v = pin[ih * 123 + iw];
            sIn[r][col] = v;
        }
        __syncthreads();
        #pragma unroll 1
        for (int kh = 0; kh < 3; kh++) {
            const float* row = &sIn[ty * 2 + kh][tx * 8];
            float in[9];
            #pragma unroll
            for (int i = 0; i < 9; i++) in[i] = row[i];
            unsigned long long p01[3], p23[3];
            #pragma unroll
            for (int kw = 0; kw < 3; kw++) {
                p01[kw] = pk(in[kw], in[kw + 2]);
                p23[kw] = pk(in[kw + 4], in[kw + 6]);
            }
            #pragma unroll
            for (int oc = 0; oc < 15; oc++) {
                #pragma unroll
                for (int kw = 0; kw < 3; kw++) {
                    unsigned long long wv = sW2[oc][c][kh][kw];
                    ffma2(acc2[oc][0], p01[kw], wv);
                    ffma2(acc2[oc][1], p23[kw], wv);
                }
            }
        }
    }

    // bias + relu -> smem (conv cols 0..61)
    #pragma unroll
    for (int oc = 0; oc < 15; oc++) {
        float bv = bias[oc];
        float2 v0 = upk(acc2[oc][0]);
        float2 v1 = upk(acc2[oc][1]);
        float vals[4] = {v0.x, v0.y, v1.x, v1.y};
        #pragma unroll
        for (int j = 0; j < 4; j++) {
            int cl = tx * 4 + j;
            if (cl < 62) sOut[oc][ty][cl] = fmaxf(vals[j] + bv, 0.f);
        }
    }
    __syncthreads();

    // fused maxpool -> g_pool2 [256,15,61,61]
    if (ty < 7) {
        int pr = oh0 + ty;
        if (pr < 61) {
            #pragma unroll
            for (int oc = 0; oc < 15; oc++) {
                #pragma unroll
                for (int j = 0; j < 4; j++) {
                    int cl = tx * 4 + j;
                    if (cl > 60) continue;
                    float m = fmaxf(fmaxf(sOut[oc][ty][cl], sOut[oc][ty][cl + 1]),
                                    fmaxf(sOut[oc][ty + 1][cl], sOut[oc][ty + 1][cl + 1]));
                    g_pool2[(((size_t)b * 15 + oc) * 61 + pr) * 61 + cl] = m;
                }
            }
        }
    }
}

// ---------------- fc1 split-K GEMM: [256,55815] x [120,55815]^T ----------------
// grid (4 M-tiles, 37 K-chunks) = 148 blocks; tile 64M x 120N; 256 threads
// f32x2 along K (even/odd lanes), LDS.64 operands
__global__ __launch_bounds__(256) void fc1_kernel(const float* __restrict__ W)
{
    __shared__ float sA[64][18];
    __shared__ float sW[128][18];
    const int m0 = blockIdx.x * 64;
    const int ks = blockIdx.y;
    const int kbeg = ks * KCHUNK;
    const int kend = (kbeg + KCHUNK < KDIM) ? kbeg + KCHUNK : KDIM;
    const int tid = threadIdx.x;
    const int tx = tid & 15, ty = tid >> 4;

    unsigned long long acc2[4][8];
    #pragma unroll
    for (int i = 0; i < 4; i++)
        #pragma unroll
        for (int j = 0; j < 8; j++) acc2[i][j] = 0ull;

    const float* A = g_pool2;

    for (int k0 = kbeg; k0 < kend; k0 += 16) {
        #pragma unroll
        for (int i = tid; i < 64 * 16; i += 256) {
            int m = i >> 4, kk = i & 15;
            int k = k0 + kk;
            sA[m][kk] = (k < kend) ? A[(size_t)(m0 + m) * KDIM + k] : 0.f;
        }
        #pragma unroll
        for (int i = tid; i < 128 * 16; i += 256) {
            int n = i >> 4, kk = i & 15;
            int k = k0 + kk;
            sW[n][kk] = (n < 120 && k < kend) ? W[(size_t)n * KDIM + k] : 0.f;
        }
        __syncthreads();
        #pragma unroll
        for (int kk = 0; kk < 16; kk += 2) {
            unsigned long long a2[4], w2[8];
            #pragma unroll
            for (int i = 0; i < 4; i++)
                a2[i] = *reinterpret_cast<const unsigned long long*>(&sA[ty * 4 + i][kk]);
            #pragma unroll
            for (int j = 0; j < 8; j++)
                w2[j] = *reinterpret_cast<const unsigned long long*>(&sW[tx + 16 * j][kk]);
            #pragma unroll
            for (int i = 0; i < 4; i++)
                #pragma unroll
                for (int j = 0; j < 8; j++)
                    ffma2(acc2[i][j], a2[i], w2[j]);
        }
        __syncthreads();
    }

    #pragma unroll
    for (int i = 0; i < 4; i++) {
        int m = m0 + ty * 4 + i;
        #pragma unroll
        for (int j = 0; j < 8; j++) {
            int n = tx + 16 * j;
            if (n < 120) {
                float2 v = upk(acc2[i][j]);
                g_part[((size_t)ks * BATCH + m) * 120 + n] = v.x + v.y;
            }
        }
    }
}

__global__ void fc1_reduce_kernel(const float* __restrict__ fc1_b)
{
    int idx = blockIdx.x * blockDim.x + threadIdx.x;
    if (idx >= BATCH * 120) return;
    int n = idx % 120;
    float s = fc1_b[n];
    #pragma unroll 1
    for (int ks = 0; ks < KSPLIT; ks++)
        s += g_part[(size_t)ks * BATCH * 120 + idx];
    g_h1[idx] = fmaxf(s, 0.f);
}

// ---------------- fc2 + fc3 + ParameterizedLayer + sigmoid ----------------
__global__ __launch_bounds__(128) void head_kernel(
    const float* __restrict__ fc2_w, const float* __restrict__ fc2_b,
    const float* __restrict__ fc3_w, const float* __restrict__ fc3_b,
    const float* __restrict__ pl_w, const float* __restrict__ pl_b,
    const float* __restrict__ pl_scale, const float* __restrict__ pl_bias)
{
    const int m = blockIdx.x;
    const int t = threadIdx.x;
    __shared__ float sh[120];
    __shared__ float sfeat[84];
    if (t < 120) sh[t] = g_h1[m * 120 + t];
    __syncthreads();
    if (t < 84) {
        float s = fc2_b[t];
        const float* wr = fc2_w + t * 120;
        #pragma unroll
        for (int k = 0; k < 120; k++) s = fmaf(sh[k], wr[k], s);
        g_feat[m * 84 + t] = s;
        sfeat[t] = s * fc3_w[t];
    }
    __syncthreads();
    if (t == 0) {
        float l = fc3_b[0];
        #pragma unroll
        for (int k = 0; k < 84; k++) l += sfeat[k];
        float z = tanhf(l * pl_w[0] + pl_b[0]) * pl_scale[0] + pl_bias[0];
        g_probs[m] = 1.f / (1.f + expf(-z));
    }
}

// ---------------- cosine-sign adjacency + degree-weighted aggregation ----------------
// sim >= 0  <=>  dot >= 0 (denominator strictly positive); exclude diagonal.
__global__ __launch_bounds__(256) void graph_kernel(float* __restrict__ out)
{
    const int i = blockIdx.x;
    const int j = threadIdx.x;
    __shared__ float sf[84];
    __shared__ float rc[8], rs[8];
    if (j < 84) sf[j] = g_feat[i * 84 + j];
    __syncthreads();

    const float* fj = g_feat + j * 84;
    float dot = 0.f;
    #pragma unroll
    for (int k = 0; k < 84; k++) dot = fmaf(sf[k], fj[k], dot);

    const bool adj = (dot >= 0.f) && (j != i);
    float c = adj ? 1.f : 0.f;
    float s = adj ? g_probs[j] : 0.f;
    #pragma unroll
    for (int o = 16; o > 0; o >>= 1) {
        c += __shfl_down_sync(0xffffffffu, c, o);
        s += __shfl_down_sync(0xffffffffu, s, o);
    }
    const int lane = j & 31, wrp = j >> 5;
    if (lane == 0) { rc[wrp] = c; rs[wrp] = s; }
    __syncthreads();
    if (j == 0) {
        float deg = 0.f, ss = 0.f;
        #pragma unroll
        for (int w2 = 0; w2 < 8; w2++) { deg += rc[w2]; ss += rs[w2]; }
        float neigh = (deg > 0.f) ? ss / fmaxf(deg, 1.f) : 0.f;
        float agg = (g_probs[i] + neigh) / (1.f + deg);
        out[2 * i]     = agg;
        out[2 * i + 1] = 1.f - agg;
    }
}

// ---------------- launch ----------------
extern "C" void kernel_launch(void* const* d_in, const int* in_sizes, int n_in,
                              void* d_out, int out_size)
{
    const float* x       = (const float*)d_in[0];
    const float* conv1_w = (const float*)d_in[1];
    const float* conv1_b = (const float*)d_in[2];
    const float* conv2_w = (const float*)d_in[3];
    const float* conv2_b = (const float*)d_in[4];
    const float* fc1_w   = (const float*)d_in[5];
    const float* fc1_b   = (const float*)d_in[6];
    const float* fc2_w   = (const float*)d_in[7];
    const float* fc2_b   = (const float*)d_in[8];
    const float* fc3_w   = (const float*)d_in[9];
    const float* fc3_b   = (const float*)d_in[10];
    const float* pl_w    = (const float*)d_in[11];
    const float* pl_b    = (const float*)d_in[12];
    const float* pl_scale= (const float*)d_in[13];
    const float* pl_bias = (const float*)d_in[14];
    float* out = (float*)d_out;

    conv1_kernel<<<dim3(2, 18, BATCH), dim3(16, 8)>>>(x, conv1_w, conv1_b);
    conv2_kernel<<<dim3(1, 9, BATCH), dim3(16, 8)>>>(conv2_w, conv2_b);
    fc1_kernel<<<dim3(4, KSPLIT), 256>>>(fc1_w);
    fc1_reduce_kernel<<<(BATCH * 120 + 255) / 256, 256>>>(fc1_b);
    head_kernel<<<BATCH, 128>>>(fc2_w, fc2_b, fc3_w, fc3_b, pl_w, pl_b, pl_scale, pl_bias);
    graph_kernel<<<BATCH, 256>>>(out);
}